// round 6
// baseline (speedup 1.0000x reference)
#include <cuda_runtime.h>
#include <math.h>
#include <stdint.h>

// ---------------------------------------------------------------------------
// SNN pipeline: 4x (dual-exp IIR -> dense GEMM -> LIF w/ decaying reset)
// + final output IIR filter. Layouts are [B, F, T] with T contiguous.
// ---------------------------------------------------------------------------

#define T_LEN 300
#define BATCHN 64

// Scratch ping-pong buffers (max layer tensor = 64*500*300 floats = 38.4 MB)
__device__ float g_bufA[64 * 500 * 300];
__device__ float g_bufB[64 * 500 * 300];

// ---------------------------------------------------------------------------
// IIR only (first layer): y[t] = a1*y[t-1] + a2*y[t-2] + b*x[t]
// One thread per (b,f) row; row is contiguous (300 floats, %4==0 -> float4).
// ---------------------------------------------------------------------------
__global__ void iir_kernel(const float* __restrict__ x, float* __restrict__ y,
                           const float* __restrict__ a1v,
                           const float* __restrict__ a2v,
                           const float* __restrict__ bv,
                           int F, int rows)
{
    int r = blockIdx.x * blockDim.x + threadIdx.x;
    if (r >= rows) return;
    int f = r % F;
    float a1 = a1v[f], a2 = a2v[f], b = bv[f];
    const float4* xp = reinterpret_cast<const float4*>(x + (size_t)r * T_LEN);
    float4* yp = reinterpret_cast<float4*>(y + (size_t)r * T_LEN);
    float y1 = 0.f, y2 = 0.f;
#pragma unroll 5
    for (int q = 0; q < T_LEN / 4; q++) {
        float4 xv = xp[q];
        float4 ov;
        float yv;
        yv = a1 * y1 + a2 * y2 + b * xv.x; ov.x = yv; y2 = y1; y1 = yv;
        yv = a1 * y1 + a2 * y2 + b * xv.y; ov.y = yv; y2 = y1; y1 = yv;
        yv = a1 * y1 + a2 * y2 + b * xv.z; ov.z = yv; y2 = y1; y1 = yv;
        yv = a1 * y1 + a2 * y2 + b * xv.w; ov.w = yv; y2 = y1; y1 = yv;
        yp[q] = ov;
    }
}

// ---------------------------------------------------------------------------
// Fused LIF spiking scan + next-layer IIR on the spikes.
//   v = cur + reset ; s = (v >= 1) ; reset = reset*EM - s
//   y = a1*y[t-1] + a2*y[t-2] + b*s
// ---------------------------------------------------------------------------
__global__ void lif_iir_kernel(const float* __restrict__ cur,
                               float* __restrict__ xout,
                               const float* __restrict__ a1v,
                               const float* __restrict__ a2v,
                               const float* __restrict__ bv,
                               int F, int rows, float rdecay)
{
    int r = blockIdx.x * blockDim.x + threadIdx.x;
    if (r >= rows) return;
    int f = r % F;
    float a1 = a1v[f], a2 = a2v[f], b = bv[f];
    const float4* cp = reinterpret_cast<const float4*>(cur + (size_t)r * T_LEN);
    float4* yp = reinterpret_cast<float4*>(xout + (size_t)r * T_LEN);
    float reset = 0.f, y1 = 0.f, y2 = 0.f;
#pragma unroll 5
    for (int q = 0; q < T_LEN / 4; q++) {
        float4 cv = cp[q];
        float4 ov;
        float v, s, yv;
        v = cv.x + reset; s = (v >= 1.0f) ? 1.0f : 0.0f; reset = reset * rdecay - s;
        yv = a1 * y1 + a2 * y2 + b * s; ov.x = yv; y2 = y1; y1 = yv;
        v = cv.y + reset; s = (v >= 1.0f) ? 1.0f : 0.0f; reset = reset * rdecay - s;
        yv = a1 * y1 + a2 * y2 + b * s; ov.y = yv; y2 = y1; y1 = yv;
        v = cv.z + reset; s = (v >= 1.0f) ? 1.0f : 0.0f; reset = reset * rdecay - s;
        yv = a1 * y1 + a2 * y2 + b * s; ov.z = yv; y2 = y1; y1 = yv;
        v = cv.w + reset; s = (v >= 1.0f) ? 1.0f : 0.0f; reset = reset * rdecay - s;
        yv = a1 * y1 + a2 * y2 + b * s; ov.w = yv; y2 = y1; y1 = yv;
        yp[q] = ov;
    }
}

// ---------------------------------------------------------------------------
// Final layer: LIF scan -> s4 (output 0) and fixed dual-exp IIR -> filt (output 1)
// ---------------------------------------------------------------------------
__global__ void lif_final_kernel(const float* __restrict__ cur,
                                 float* __restrict__ s4,
                                 float* __restrict__ filt,
                                 int rows, float rdecay,
                                 float A1, float A2, float Bc)
{
    int r = blockIdx.x * blockDim.x + threadIdx.x;
    if (r >= rows) return;
    const float4* cp = reinterpret_cast<const float4*>(cur + (size_t)r * T_LEN);
    float4* sp = reinterpret_cast<float4*>(s4 + (size_t)r * T_LEN);
    float4* fp = reinterpret_cast<float4*>(filt + (size_t)r * T_LEN);
    float reset = 0.f, y1 = 0.f, y2 = 0.f;
#pragma unroll 5
    for (int q = 0; q < T_LEN / 4; q++) {
        float4 cv = cp[q];
        float4 sv, fv;
        float v, s, yv;
        v = cv.x + reset; s = (v >= 1.0f) ? 1.0f : 0.0f; reset = reset * rdecay - s;
        yv = A1 * y1 + A2 * y2 + Bc * s; sv.x = s; fv.x = yv; y2 = y1; y1 = yv;
        v = cv.y + reset; s = (v >= 1.0f) ? 1.0f : 0.0f; reset = reset * rdecay - s;
        yv = A1 * y1 + A2 * y2 + Bc * s; sv.y = s; fv.y = yv; y2 = y1; y1 = yv;
        v = cv.z + reset; s = (v >= 1.0f) ? 1.0f : 0.0f; reset = reset * rdecay - s;
        yv = A1 * y1 + A2 * y2 + Bc * s; sv.z = s; fv.z = yv; y2 = y1; y1 = yv;
        v = cv.w + reset; s = (v >= 1.0f) ? 1.0f : 0.0f; reset = reset * rdecay - s;
        yv = A1 * y1 + A2 * y2 + Bc * s; sv.w = s; fv.w = yv; y2 = y1; y1 = yv;
        sp[q] = sv;
        fp[q] = fv;
    }
}

// ---------------------------------------------------------------------------
// Batched SGEMM + bias: for each b, C_b[M, T] = W[M, K] @ X_b[K, T] + bias
// W row-major (K contiguous), X_b row-major (T contiguous). fp32 accumulate.
// Tiles: BM=128, BN=64, BK=16; 256 threads; 8x4 register tile per thread.
// A reads from smem are warp-broadcast (2 distinct addrs/warp) -> ~free.
// ---------------------------------------------------------------------------
#define BM 128
#define BN 64
#define BK 16

__global__ __launch_bounds__(256) void sgemm_bias_kernel(
    const float* __restrict__ W, const float* __restrict__ X,
    const float* __restrict__ bias, float* __restrict__ C,
    int M, int K)
{
    __shared__ float As[BK][BM];      // transposed: As[k][m]
    __shared__ float Bs[BK][BN + 4];  // +4 pad to break store-phase conflicts

    int b = blockIdx.z;
    const float* Xb = X + (size_t)b * K * T_LEN;
    float* Cb = C + (size_t)b * M * T_LEN;
    int m0 = blockIdx.y * BM;
    int t0 = blockIdx.x * BN;
    int tid = threadIdx.x;
    int tx = tid & 15;   // n direction (4 cols each)
    int ty = tid >> 4;   // m direction (8 rows each)

    float acc[8][4];
#pragma unroll
    for (int i = 0; i < 8; i++)
#pragma unroll
        for (int j = 0; j < 4; j++) acc[i][j] = 0.f;

    for (int k0 = 0; k0 < K; k0 += BK) {
        // --- load A tile (128x16): 512 float4 vectors, 2 per thread ---
#pragma unroll
        for (int it = 0; it < 2; it++) {
            int v = tid + it * 256;
            int m = v >> 2;            // 0..127
            int kq = (v & 3) << 2;     // 0,4,8,12
            float4 av = make_float4(0.f, 0.f, 0.f, 0.f);
            int gm = m0 + m, gk = k0 + kq;
            // K is always a multiple of 4 here (300/500/200), so gk<K => gk+3<K
            if (gm < M && gk < K)
                av = *reinterpret_cast<const float4*>(W + (size_t)gm * K + gk);
            As[kq + 0][m] = av.x;
            As[kq + 1][m] = av.y;
            As[kq + 2][m] = av.z;
            As[kq + 3][m] = av.w;
        }
        // --- load B tile (16x64): 256 float4 vectors, 1 per thread ---
        {
            int kB = tid >> 4;
            int n4 = (tid & 15) << 2;
            float4 bv = make_float4(0.f, 0.f, 0.f, 0.f);
            int gk = k0 + kB, gt = t0 + n4;
            // T=300 is a multiple of 4 and gt%4==0, so gt<T => gt+3<T
            if (gk < K && gt < T_LEN)
                bv = *reinterpret_cast<const float4*>(Xb + (size_t)gk * T_LEN + gt);
            *reinterpret_cast<float4*>(&Bs[kB][n4]) = bv;
        }
        __syncthreads();

#pragma unroll
        for (int kk = 0; kk < BK; kk++) {
            float4 a0 = *reinterpret_cast<const float4*>(&As[kk][ty * 8]);
            float4 a1 = *reinterpret_cast<const float4*>(&As[kk][ty * 8 + 4]);
            float4 bb = *reinterpret_cast<const float4*>(&Bs[kk][tx * 4]);
            float a[8] = {a0.x, a0.y, a0.z, a0.w, a1.x, a1.y, a1.z, a1.w};
            float bs[4] = {bb.x, bb.y, bb.z, bb.w};
#pragma unroll
            for (int i = 0; i < 8; i++)
#pragma unroll
                for (int j = 0; j < 4; j++)
                    acc[i][j] += a[i] * bs[j];
        }
        __syncthreads();
    }

    int gt = t0 + tx * 4;
    if (gt < T_LEN) {
#pragma unroll
        for (int i = 0; i < 8; i++) {
            int gm = m0 + ty * 8 + i;
            if (gm < M) {
                float bi = bias[gm];
                float4 o = make_float4(acc[i][0] + bi, acc[i][1] + bi,
                                       acc[i][2] + bi, acc[i][3] + bi);
                *reinterpret_cast<float4*>(Cb + (size_t)gm * T_LEN + gt) = o;
            }
        }
    }
}

// ---------------------------------------------------------------------------
// Host launcher
// ---------------------------------------------------------------------------
extern "C" void kernel_launch(void* const* d_in, const int* in_sizes, int n_in,
                              void* d_out, int out_size)
{
    (void)in_sizes; (void)n_in; (void)out_size;

    // Inputs (metadata order matches the reference signature)
    const float* inputs = (const float*)d_in[0];
    const float* a1_1 = (const float*)d_in[1];
    const float* a2_1 = (const float*)d_in[2];
    const float* b_1  = (const float*)d_in[3];
    const float* W1   = (const float*)d_in[4];
    const float* bias1= (const float*)d_in[5];
    const float* a1_2 = (const float*)d_in[6];
    const float* a2_2 = (const float*)d_in[7];
    const float* b_2  = (const float*)d_in[8];
    const float* W2   = (const float*)d_in[9];
    const float* bias2= (const float*)d_in[10];
    const float* a1_3 = (const float*)d_in[11];
    const float* a2_3 = (const float*)d_in[12];
    const float* b_3  = (const float*)d_in[13];
    const float* W3   = (const float*)d_in[14];
    const float* bias3= (const float*)d_in[15];
    const float* a1_4 = (const float*)d_in[16];
    const float* a2_4 = (const float*)d_in[17];
    const float* b_4  = (const float*)d_in[18];
    const float* W4   = (const float*)d_in[19];
    const float* bias4= (const float*)d_in[20];

    float* out = (float*)d_out;
    float* s4_out   = out;                         // [64, 300, 300]
    float* filt_out = out + (size_t)BATCHN * 300 * T_LEN;

    float *bufA, *bufB;
    cudaGetSymbolAddress((void**)&bufA, g_bufA);
    cudaGetSymbolAddress((void**)&bufB, g_bufB);

    // Constants exactly as the reference builds them (double -> f32 cast)
    double EMd = exp(-1.0 / 8.0);
    double ESd = exp(-1.0 / 2.0);
    float fEM = (float)EMd;                       // RESET_DECAY
    float fA1 = (float)(EMd + ESd);
    float fA2 = (float)(-(EMd * ESd));
    float fB  = (float)((8.0 / 6.0) * (EMd - ESd));

    const int F0 = 300, F1 = 500, F2 = 200, F3 = 500, F4 = 300;
    const int THREADS = 256;
    auto blocks = [](int rows) { return (rows + 255) / 256; };
    auto ggrid = [](int M) {
        return dim3((T_LEN + BN - 1) / BN, (M + BM - 1) / BM, BATCHN);
    };

    // Layer 1
    int rows0 = BATCHN * F0;
    iir_kernel<<<blocks(rows0), THREADS>>>(inputs, bufA, a1_1, a2_1, b_1, F0, rows0);
    sgemm_bias_kernel<<<ggrid(F1), 256>>>(W1, bufA, bias1, bufB, F1, F0);

    // Layer 2 (LIF of layer-1 currents fused with layer-2 input IIR)
    int rows1 = BATCHN * F1;
    lif_iir_kernel<<<blocks(rows1), THREADS>>>(bufB, bufA, a1_2, a2_2, b_2, F1, rows1, fEM);
    sgemm_bias_kernel<<<ggrid(F2), 256>>>(W2, bufA, bias2, bufB, F2, F1);

    // Layer 3
    int rows2 = BATCHN * F2;
    lif_iir_kernel<<<blocks(rows2), THREADS>>>(bufB, bufA, a1_3, a2_3, b_3, F2, rows2, fEM);
    sgemm_bias_kernel<<<ggrid(F3), 256>>>(W3, bufA, bias3, bufB, F3, F2);

    // Layer 4
    int rows3 = BATCHN * F3;
    lif_iir_kernel<<<blocks(rows3), THREADS>>>(bufB, bufA, a1_4, a2_4, b_4, F3, rows3, fEM);
    sgemm_bias_kernel<<<ggrid(F4), 256>>>(W4, bufA, bias4, bufB, F4, F3);

    // Final: LIF -> s4, fixed output IIR -> filt
    int rows4 = BATCHN * F4;
    lif_final_kernel<<<blocks(rows4), THREADS>>>(bufB, s4_out, filt_out, rows4,
                                                 fEM, fA1, fA2, fB);
}

// round 9
// speedup vs baseline: 1.6994x; 1.6994x over previous
#include <cuda_runtime.h>
#include <math.h>
#include <stdint.h>

// ---------------------------------------------------------------------------
// SNN pipeline: 4x (dual-exp IIR -> dense GEMM -> LIF w/ decaying reset)
// + final output IIR filter. Layouts are [B, F, T] with T contiguous.
// GEMM inner loop uses packed fma.rn.f32x2 (FFMA2) -> 2 FMAs per issue slot.
// ---------------------------------------------------------------------------

#define T_LEN 300
#define BATCHN 64

// Scratch ping-pong buffers (max layer tensor = 64*500*300 floats = 38.4 MB)
__device__ float g_bufA[64 * 500 * 300];
__device__ float g_bufB[64 * 500 * 300];

// ---------------------------------------------------------------------------
// IIR only (first layer): y[t] = a1*y[t-1] + a2*y[t-2] + b*x[t]
// ---------------------------------------------------------------------------
__global__ void iir_kernel(const float* __restrict__ x, float* __restrict__ y,
                           const float* __restrict__ a1v,
                           const float* __restrict__ a2v,
                           const float* __restrict__ bv,
                           int F, int rows)
{
    int r = blockIdx.x * blockDim.x + threadIdx.x;
    if (r >= rows) return;
    int f = r % F;
    float a1 = a1v[f], a2 = a2v[f], b = bv[f];
    const float4* xp = reinterpret_cast<const float4*>(x + (size_t)r * T_LEN);
    float4* yp = reinterpret_cast<float4*>(y + (size_t)r * T_LEN);
    float y1 = 0.f, y2 = 0.f;
#pragma unroll 5
    for (int q = 0; q < T_LEN / 4; q++) {
        float4 xv = xp[q];
        float4 ov;
        float yv;
        yv = a1 * y1 + a2 * y2 + b * xv.x; ov.x = yv; y2 = y1; y1 = yv;
        yv = a1 * y1 + a2 * y2 + b * xv.y; ov.y = yv; y2 = y1; y1 = yv;
        yv = a1 * y1 + a2 * y2 + b * xv.z; ov.z = yv; y2 = y1; y1 = yv;
        yv = a1 * y1 + a2 * y2 + b * xv.w; ov.w = yv; y2 = y1; y1 = yv;
        yp[q] = ov;
    }
}

// ---------------------------------------------------------------------------
// Fused LIF spiking scan + next-layer IIR on the spikes.
// ---------------------------------------------------------------------------
__global__ void lif_iir_kernel(const float* __restrict__ cur,
                               float* __restrict__ xout,
                               const float* __restrict__ a1v,
                               const float* __restrict__ a2v,
                               const float* __restrict__ bv,
                               int F, int rows, float rdecay)
{
    int r = blockIdx.x * blockDim.x + threadIdx.x;
    if (r >= rows) return;
    int f = r % F;
    float a1 = a1v[f], a2 = a2v[f], b = bv[f];
    const float4* cp = reinterpret_cast<const float4*>(cur + (size_t)r * T_LEN);
    float4* yp = reinterpret_cast<float4*>(xout + (size_t)r * T_LEN);
    float reset = 0.f, y1 = 0.f, y2 = 0.f;
#pragma unroll 5
    for (int q = 0; q < T_LEN / 4; q++) {
        float4 cv = cp[q];
        float4 ov;
        float v, s, yv;
        v = cv.x + reset; s = (v >= 1.0f) ? 1.0f : 0.0f; reset = reset * rdecay - s;
        yv = a1 * y1 + a2 * y2 + b * s; ov.x = yv; y2 = y1; y1 = yv;
        v = cv.y + reset; s = (v >= 1.0f) ? 1.0f : 0.0f; reset = reset * rdecay - s;
        yv = a1 * y1 + a2 * y2 + b * s; ov.y = yv; y2 = y1; y1 = yv;
        v = cv.z + reset; s = (v >= 1.0f) ? 1.0f : 0.0f; reset = reset * rdecay - s;
        yv = a1 * y1 + a2 * y2 + b * s; ov.z = yv; y2 = y1; y1 = yv;
        v = cv.w + reset; s = (v >= 1.0f) ? 1.0f : 0.0f; reset = reset * rdecay - s;
        yv = a1 * y1 + a2 * y2 + b * s; ov.w = yv; y2 = y1; y1 = yv;
        yp[q] = ov;
    }
}

// ---------------------------------------------------------------------------
// Final layer: LIF scan -> s4 (output 0) and fixed dual-exp IIR -> filt
// ---------------------------------------------------------------------------
__global__ void lif_final_kernel(const float* __restrict__ cur,
                                 float* __restrict__ s4,
                                 float* __restrict__ filt,
                                 int rows, float rdecay,
                                 float A1, float A2, float Bc)
{
    int r = blockIdx.x * blockDim.x + threadIdx.x;
    if (r >= rows) return;
    const float4* cp = reinterpret_cast<const float4*>(cur + (size_t)r * T_LEN);
    float4* sp = reinterpret_cast<float4*>(s4 + (size_t)r * T_LEN);
    float4* fp = reinterpret_cast<float4*>(filt + (size_t)r * T_LEN);
    float reset = 0.f, y1 = 0.f, y2 = 0.f;
#pragma unroll 5
    for (int q = 0; q < T_LEN / 4; q++) {
        float4 cv = cp[q];
        float4 sv, fv;
        float v, s, yv;
        v = cv.x + reset; s = (v >= 1.0f) ? 1.0f : 0.0f; reset = reset * rdecay - s;
        yv = A1 * y1 + A2 * y2 + Bc * s; sv.x = s; fv.x = yv; y2 = y1; y1 = yv;
        v = cv.y + reset; s = (v >= 1.0f) ? 1.0f : 0.0f; reset = reset * rdecay - s;
        yv = A1 * y1 + A2 * y2 + Bc * s; sv.y = s; fv.y = yv; y2 = y1; y1 = yv;
        v = cv.z + reset; s = (v >= 1.0f) ? 1.0f : 0.0f; reset = reset * rdecay - s;
        yv = A1 * y1 + A2 * y2 + Bc * s; sv.z = s; fv.z = yv; y2 = y1; y1 = yv;
        v = cv.w + reset; s = (v >= 1.0f) ? 1.0f : 0.0f; reset = reset * rdecay - s;
        yv = A1 * y1 + A2 * y2 + Bc * s; sv.w = s; fv.w = yv; y2 = y1; y1 = yv;
        sp[q] = sv;
        fp[q] = fv;
    }
}

// ---------------------------------------------------------------------------
// Batched SGEMM + bias with packed f32x2 FMA:
// for each b, C_b[M, T] = W[M, K] @ X_b[K, T] + bias
// Tiles: BM=128, BN=64, BK=16; 256 threads; 8x4 thread tile organized as
// 4 row-PAIRS x 4 cols. A row-pairs come packed straight out of shared memory
// (transposed As -> consecutive rows); B cols are duplicated via mov.b64.
// Inner loop: 16 FFMA2 per kk = 32 FMAs at half the issue/pipe cost.
// ---------------------------------------------------------------------------
#define BM 128
#define BN 64
#define BK 16

__global__ __launch_bounds__(256) void sgemm_bias_kernel(
    const float* __restrict__ W, const float* __restrict__ X,
    const float* __restrict__ bias, float* __restrict__ C,
    int M, int K)
{
    __shared__ __align__(16) float As[BK][BM];      // transposed: As[k][m]
    __shared__ __align__(16) float Bs[BK][BN + 4];  // row stride 272B (16B aligned)

    int b = blockIdx.z;
    const float* Xb = X + (size_t)b * K * T_LEN;
    float* Cb = C + (size_t)b * M * T_LEN;
    int m0 = blockIdx.y * BM;
    int t0 = blockIdx.x * BN;
    int tid = threadIdx.x;
    int tx = tid & 15;   // n direction (4 cols each)
    int ty = tid >> 4;   // m direction (8 rows = 4 pairs each)

    // acc2[p][j]: packed f32x2 accumulator; lo = row 2p, hi = row 2p+1 (within
    // this thread's 8-row strip), column j.
    unsigned long long acc2[4][4];
#pragma unroll
    for (int p = 0; p < 4; p++)
#pragma unroll
        for (int j = 0; j < 4; j++) acc2[p][j] = 0ULL;

    for (int k0 = 0; k0 < K; k0 += BK) {
        // --- load A tile (128x16): 512 float4 vectors, 2 per thread ---
#pragma unroll
        for (int it = 0; it < 2; it++) {
            int v = tid + it * 256;
            int m = v >> 2;            // 0..127
            int kq = (v & 3) << 2;     // 0,4,8,12
            float4 av = make_float4(0.f, 0.f, 0.f, 0.f);
            int gm = m0 + m, gk = k0 + kq;
            // K is a multiple of 4 (300/500/200), so gk<K => gk+3<K
            if (gm < M && gk < K)
                av = *reinterpret_cast<const float4*>(W + (size_t)gm * K + gk);
            As[kq + 0][m] = av.x;
            As[kq + 1][m] = av.y;
            As[kq + 2][m] = av.z;
            As[kq + 3][m] = av.w;
        }
        // --- load B tile (16x64): 256 float4 vectors, 1 per thread ---
        {
            int kB = tid >> 4;
            int n4 = (tid & 15) << 2;
            float4 bv = make_float4(0.f, 0.f, 0.f, 0.f);
            int gk = k0 + kB, gt = t0 + n4;
            if (gk < K && gt < T_LEN)
                bv = *reinterpret_cast<const float4*>(Xb + (size_t)gk * T_LEN + gt);
            *reinterpret_cast<float4*>(&Bs[kB][n4]) = bv;
        }
        __syncthreads();

#pragma unroll
        for (int kk = 0; kk < BK; kk++) {
            // A row-pairs: two LDS.128 -> 4 aligned 64-bit packed (f32,f32)
            ulonglong2 A01 = *reinterpret_cast<const ulonglong2*>(&As[kk][ty * 8]);
            ulonglong2 A23 = *reinterpret_cast<const ulonglong2*>(&As[kk][ty * 8 + 4]);
            unsigned long long ap[4] = {A01.x, A01.y, A23.x, A23.y};
            // B columns, duplicated into both halves
            float4 bb = *reinterpret_cast<const float4*>(&Bs[kk][tx * 4]);
            unsigned long long bd[4];
            unsigned int bu;
            bu = __float_as_uint(bb.x);
            asm("mov.b64 %0, {%1, %1};" : "=l"(bd[0]) : "r"(bu));
            bu = __float_as_uint(bb.y);
            asm("mov.b64 %0, {%1, %1};" : "=l"(bd[1]) : "r"(bu));
            bu = __float_as_uint(bb.z);
            asm("mov.b64 %0, {%1, %1};" : "=l"(bd[2]) : "r"(bu));
            bu = __float_as_uint(bb.w);
            asm("mov.b64 %0, {%1, %1};" : "=l"(bd[3]) : "r"(bu));
#pragma unroll
            for (int p = 0; p < 4; p++)
#pragma unroll
                for (int j = 0; j < 4; j++)
                    asm("fma.rn.f32x2 %0, %1, %2, %0;"
                        : "+l"(acc2[p][j]) : "l"(ap[p]), "l"(bd[j]));
        }
        __syncthreads();
    }

    // Epilogue: unpack pairs, add bias, store float4 per row
    int gt = t0 + tx * 4;
    if (gt < T_LEN) {
#pragma unroll
        for (int p = 0; p < 4; p++) {
            float lo[4], hi[4];
#pragma unroll
            for (int j = 0; j < 4; j++) {
                unsigned int ulo, uhi;
                asm("mov.b64 {%0, %1}, %2;" : "=r"(ulo), "=r"(uhi) : "l"(acc2[p][j]));
                lo[j] = __uint_as_float(ulo);
                hi[j] = __uint_as_float(uhi);
            }
            int gmlo = m0 + ty * 8 + 2 * p;
            int gmhi = gmlo + 1;
            if (gmlo < M) {
                float bi = bias[gmlo];
                float4 o = make_float4(lo[0] + bi, lo[1] + bi, lo[2] + bi, lo[3] + bi);
                *reinterpret_cast<float4*>(Cb + (size_t)gmlo * T_LEN + gt) = o;
            }
            if (gmhi < M) {
                float bi = bias[gmhi];
                float4 o = make_float4(hi[0] + bi, hi[1] + bi, hi[2] + bi, hi[3] + bi);
                *reinterpret_cast<float4*>(Cb + (size_t)gmhi * T_LEN + gt) = o;
            }
        }
    }
}

// ---------------------------------------------------------------------------
// Host launcher
// ---------------------------------------------------------------------------
extern "C" void kernel_launch(void* const* d_in, const int* in_sizes, int n_in,
                              void* d_out, int out_size)
{
    (void)in_sizes; (void)n_in; (void)out_size;

    const float* inputs = (const float*)d_in[0];
    const float* a1_1 = (const float*)d_in[1];
    const float* a2_1 = (const float*)d_in[2];
    const float* b_1  = (const float*)d_in[3];
    const float* W1   = (const float*)d_in[4];
    const float* bias1= (const float*)d_in[5];
    const float* a1_2 = (const float*)d_in[6];
    const float* a2_2 = (const float*)d_in[7];
    const float* b_2  = (const float*)d_in[8];
    const float* W2   = (const float*)d_in[9];
    const float* bias2= (const float*)d_in[10];
    const float* a1_3 = (const float*)d_in[11];
    const float* a2_3 = (const float*)d_in[12];
    const float* b_3  = (const float*)d_in[13];
    const float* W3   = (const float*)d_in[14];
    const float* bias3= (const float*)d_in[15];
    const float* a1_4 = (const float*)d_in[16];
    const float* a2_4 = (const float*)d_in[17];
    const float* b_4  = (const float*)d_in[18];
    const float* W4   = (const float*)d_in[19];
    const float* bias4= (const float*)d_in[20];

    float* out = (float*)d_out;
    float* s4_out   = out;                         // [64, 300, 300]
    float* filt_out = out + (size_t)BATCHN * 300 * T_LEN;

    float *bufA, *bufB;
    cudaGetSymbolAddress((void**)&bufA, g_bufA);
    cudaGetSymbolAddress((void**)&bufB, g_bufB);

    // Constants exactly as the reference builds them (double -> f32 cast)
    double EMd = exp(-1.0 / 8.0);
    double ESd = exp(-1.0 / 2.0);
    float fEM = (float)EMd;                       // RESET_DECAY
    float fA1 = (float)(EMd + ESd);
    float fA2 = (float)(-(EMd * ESd));
    float fB  = (float)((8.0 / 6.0) * (EMd - ESd));

    const int F0 = 300, F1 = 500, F2 = 200, F3 = 500, F4 = 300;
    const int THREADS = 256;
    auto blocks = [](int rows) { return (rows + 255) / 256; };
    auto ggrid = [](int M) {
        return dim3((T_LEN + BN - 1) / BN, (M + BM - 1) / BM, BATCHN);
    };

    // Layer 1
    int rows0 = BATCHN * F0;
    iir_kernel<<<blocks(rows0), THREADS>>>(inputs, bufA, a1_1, a2_1, b_1, F0, rows0);
    sgemm_bias_kernel<<<ggrid(F1), 256>>>(W1, bufA, bias1, bufB, F1, F0);

    // Layer 2 (LIF of layer-1 currents fused with layer-2 input IIR)
    int rows1 = BATCHN * F1;
    lif_iir_kernel<<<blocks(rows1), THREADS>>>(bufB, bufA, a1_2, a2_2, b_2, F1, rows1, fEM);
    sgemm_bias_kernel<<<ggrid(F2), 256>>>(W2, bufA, bias2, bufB, F2, F1);

    // Layer 3
    int rows2 = BATCHN * F2;
    lif_iir_kernel<<<blocks(rows2), THREADS>>>(bufB, bufA, a1_3, a2_3, b_3, F2, rows2, fEM);
    sgemm_bias_kernel<<<ggrid(F3), 256>>>(W3, bufA, bias3, bufB, F3, F2);

    // Layer 4
    int rows3 = BATCHN * F3;
    lif_iir_kernel<<<blocks(rows3), THREADS>>>(bufB, bufA, a1_4, a2_4, b_4, F3, rows3, fEM);
    sgemm_bias_kernel<<<ggrid(F4), 256>>>(W4, bufA, bias4, bufB, F4, F3);

    // Final: LIF -> s4, fixed output IIR -> filt
    int rows4 = BATCHN * F4;
    lif_final_kernel<<<blocks(rows4), THREADS>>>(bufB, s4_out, filt_out, rows4,
                                                 fEM, fA1, fA2, fB);
}

// round 13
// speedup vs baseline: 1.9905x; 1.1713x over previous
#include <cuda_runtime.h>
#include <math.h>
#include <stdint.h>

// ---------------------------------------------------------------------------
// SNN pipeline: 4x (dual-exp IIR -> dense GEMM -> LIF w/ decaying reset)
// + final output IIR filter. Layouts are [B, F, T] with T contiguous.
// GEMM: packed fma.rn.f32x2 inner loop + cp.async double-buffered tiles
// fed from a pre-transposed, zero-padded weight copy (branch-free mainloop).
// ---------------------------------------------------------------------------

#define T_LEN 300
#define BATCHN 64

// Scratch ping-pong buffers (max layer tensor = 64*500*300 floats = 38.4 MB)
__device__ float g_bufA[64 * 500 * 300];
__device__ float g_bufB[64 * 500 * 300];
// Transposed padded weights: 4 layers at fixed 1M-float offsets
__device__ float g_Wt[4 * 1024 * 1024];

// ---------------------------------------------------------------------------
// Transpose + pad weights: Wt[k][m] = W[m][k], zero outside (K, M).
// ---------------------------------------------------------------------------
__global__ void transpose_pad_kernel(const float* __restrict__ W,
                                     float* __restrict__ Wt,
                                     int M, int K, int Mpad, int Kpad)
{
    int idx = blockIdx.x * blockDim.x + threadIdx.x;
    if (idx >= Mpad * Kpad) return;
    int m = idx % Mpad;
    int k = idx / Mpad;
    float v = 0.f;
    if (m < M && k < K) v = W[(size_t)m * K + k];
    Wt[(size_t)k * Mpad + m] = v;
}

// ---------------------------------------------------------------------------
// IIR only (first layer): y[t] = a1*y[t-1] + a2*y[t-2] + b*x[t]
// ---------------------------------------------------------------------------
__global__ void iir_kernel(const float* __restrict__ x, float* __restrict__ y,
                           const float* __restrict__ a1v,
                           const float* __restrict__ a2v,
                           const float* __restrict__ bv,
                           int F, int rows)
{
    int r = blockIdx.x * blockDim.x + threadIdx.x;
    if (r >= rows) return;
    int f = r % F;
    float a1 = a1v[f], a2 = a2v[f], b = bv[f];
    const float4* xp = reinterpret_cast<const float4*>(x + (size_t)r * T_LEN);
    float4* yp = reinterpret_cast<float4*>(y + (size_t)r * T_LEN);
    float y1 = 0.f, y2 = 0.f;
#pragma unroll 5
    for (int q = 0; q < T_LEN / 4; q++) {
        float4 xv = xp[q];
        float4 ov;
        float yv;
        yv = a1 * y1 + a2 * y2 + b * xv.x; ov.x = yv; y2 = y1; y1 = yv;
        yv = a1 * y1 + a2 * y2 + b * xv.y; ov.y = yv; y2 = y1; y1 = yv;
        yv = a1 * y1 + a2 * y2 + b * xv.z; ov.z = yv; y2 = y1; y1 = yv;
        yv = a1 * y1 + a2 * y2 + b * xv.w; ov.w = yv; y2 = y1; y1 = yv;
        yp[q] = ov;
    }
}

// ---------------------------------------------------------------------------
// Fused LIF spiking scan + next-layer IIR on the spikes.
// ---------------------------------------------------------------------------
__global__ void lif_iir_kernel(const float* __restrict__ cur,
                               float* __restrict__ xout,
                               const float* __restrict__ a1v,
                               const float* __restrict__ a2v,
                               const float* __restrict__ bv,
                               int F, int rows, float rdecay)
{
    int r = blockIdx.x * blockDim.x + threadIdx.x;
    if (r >= rows) return;
    int f = r % F;
    float a1 = a1v[f], a2 = a2v[f], b = bv[f];
    const float4* cp = reinterpret_cast<const float4*>(cur + (size_t)r * T_LEN);
    float4* yp = reinterpret_cast<float4*>(xout + (size_t)r * T_LEN);
    float reset = 0.f, y1 = 0.f, y2 = 0.f;
#pragma unroll 5
    for (int q = 0; q < T_LEN / 4; q++) {
        float4 cv = cp[q];
        float4 ov;
        float v, s, yv;
        v = cv.x + reset; s = (v >= 1.0f) ? 1.0f : 0.0f; reset = reset * rdecay - s;
        yv = a1 * y1 + a2 * y2 + b * s; ov.x = yv; y2 = y1; y1 = yv;
        v = cv.y + reset; s = (v >= 1.0f) ? 1.0f : 0.0f; reset = reset * rdecay - s;
        yv = a1 * y1 + a2 * y2 + b * s; ov.y = yv; y2 = y1; y1 = yv;
        v = cv.z + reset; s = (v >= 1.0f) ? 1.0f : 0.0f; reset = reset * rdecay - s;
        yv = a1 * y1 + a2 * y2 + b * s; ov.z = yv; y2 = y1; y1 = yv;
        v = cv.w + reset; s = (v >= 1.0f) ? 1.0f : 0.0f; reset = reset * rdecay - s;
        yv = a1 * y1 + a2 * y2 + b * s; ov.w = yv; y2 = y1; y1 = yv;
        yp[q] = ov;
    }
}

// ---------------------------------------------------------------------------
// Final layer: LIF scan -> s4 (output 0) and fixed dual-exp IIR -> filt
// ---------------------------------------------------------------------------
__global__ void lif_final_kernel(const float* __restrict__ cur,
                                 float* __restrict__ s4,
                                 float* __restrict__ filt,
                                 int rows, float rdecay,
                                 float A1, float A2, float Bc)
{
    int r = blockIdx.x * blockDim.x + threadIdx.x;
    if (r >= rows) return;
    const float4* cp = reinterpret_cast<const float4*>(cur + (size_t)r * T_LEN);
    float4* sp = reinterpret_cast<float4*>(s4 + (size_t)r * T_LEN);
    float4* fp = reinterpret_cast<float4*>(filt + (size_t)r * T_LEN);
    float reset = 0.f, y1 = 0.f, y2 = 0.f;
#pragma unroll 5
    for (int q = 0; q < T_LEN / 4; q++) {
        float4 cv = cp[q];
        float4 sv, fv;
        float v, s, yv;
        v = cv.x + reset; s = (v >= 1.0f) ? 1.0f : 0.0f; reset = reset * rdecay - s;
        yv = A1 * y1 + A2 * y2 + Bc * s; sv.x = s; fv.x = yv; y2 = y1; y1 = yv;
        v = cv.y + reset; s = (v >= 1.0f) ? 1.0f : 0.0f; reset = reset * rdecay - s;
        yv = A1 * y1 + A2 * y2 + Bc * s; sv.y = s; fv.y = yv; y2 = y1; y1 = yv;
        v = cv.z + reset; s = (v >= 1.0f) ? 1.0f : 0.0f; reset = reset * rdecay - s;
        yv = A1 * y1 + A2 * y2 + Bc * s; sv.z = s; fv.z = yv; y2 = y1; y1 = yv;
        v = cv.w + reset; s = (v >= 1.0f) ? 1.0f : 0.0f; reset = reset * rdecay - s;
        yv = A1 * y1 + A2 * y2 + Bc * s; sv.w = s; fv.w = yv; y2 = y1; y1 = yv;
        sp[q] = sv;
        fp[q] = fv;
    }
}

// ---------------------------------------------------------------------------
// Batched SGEMM + bias, FFMA2 inner loop, cp.async double-buffered tiles.
// A comes from pre-transposed padded Wt[k][m] (Kpad x Mpad, zeros in pad) ->
// unconditional 16B cp.async. B tiles use zfill for K/T edges.
// ---------------------------------------------------------------------------
#define BM 128
#define BN 64
#define BK 16

__device__ __forceinline__ unsigned smem_u32(const void* p) {
    return (unsigned)__cvta_generic_to_shared(p);
}

__global__ __launch_bounds__(256, 3) void sgemm_bias_kernel(
    const float* __restrict__ Wt, const float* __restrict__ X,
    const float* __restrict__ bias, float* __restrict__ C,
    int M, int K, int Mpad, int Kpad)
{
    __shared__ __align__(16) float As[2][BK][BM];      // As[buf][k][m]
    __shared__ __align__(16) float Bs[2][BK][BN + 4];

    int b = blockIdx.z;
    const float* Xb = X + (size_t)b * K * T_LEN;
    float* Cb = C + (size_t)b * M * T_LEN;
    int m0 = blockIdx.y * BM;
    int t0 = blockIdx.x * BN;
    int tid = threadIdx.x;
    int tx = tid & 15;   // n direction (4 cols each)
    int ty = tid >> 4;   // m direction (8 rows = 4 pairs each)

    // Precomputed load indices
    int ak1 = tid >> 5;               // rows 0..7   (it=0)
    int am1 = (tid & 31) << 2;
    int ak2 = (tid + 256) >> 5;       // rows 8..15  (it=1)
    int am2 = am1;
    int kB  = tid >> 4;
    int n4  = (tid & 15) << 2;
    int gt_ld = t0 + n4;

    unsigned long long acc2[4][4];
#pragma unroll
    for (int p = 0; p < 4; p++)
#pragma unroll
        for (int j = 0; j < 4; j++) acc2[p][j] = 0ULL;

    auto load_tiles = [&](int k0, int buf) {
        {
            const float* src = Wt + (size_t)(k0 + ak1) * Mpad + m0 + am1;
            unsigned dst = smem_u32(&As[buf][ak1][am1]);
            asm volatile("cp.async.cg.shared.global [%0], [%1], 16;"
                         :: "r"(dst), "l"(src));
        }
        {
            const float* src = Wt + (size_t)(k0 + ak2) * Mpad + m0 + am2;
            unsigned dst = smem_u32(&As[buf][ak2][am2]);
            asm volatile("cp.async.cg.shared.global [%0], [%1], 16;"
                         :: "r"(dst), "l"(src));
        }
        {
            int gk = k0 + kB;
            bool ok = (gk < K) && (gt_ld < T_LEN);
            const float* src = ok ? (Xb + (size_t)gk * T_LEN + gt_ld) : Xb;
            int sz = ok ? 16 : 0;
            unsigned dst = smem_u32(&Bs[buf][kB][n4]);
            asm volatile("cp.async.cg.shared.global [%0], [%1], 16, %2;"
                         :: "r"(dst), "l"(src), "r"(sz));
        }
        asm volatile("cp.async.commit_group;");
    };

    int nt = Kpad / BK;
    load_tiles(0, 0);
    asm volatile("cp.async.wait_group 0;");
    __syncthreads();

    int buf = 0;
    for (int t = 0; t < nt; t++) {
        if (t + 1 < nt) load_tiles((t + 1) * BK, buf ^ 1);

#pragma unroll
        for (int kk = 0; kk < BK; kk++) {
            ulonglong2 A01 = *reinterpret_cast<const ulonglong2*>(&As[buf][kk][ty * 8]);
            ulonglong2 A23 = *reinterpret_cast<const ulonglong2*>(&As[buf][kk][ty * 8 + 4]);
            unsigned long long ap[4] = {A01.x, A01.y, A23.x, A23.y};
            float4 bb = *reinterpret_cast<const float4*>(&Bs[buf][kk][tx * 4]);
            unsigned long long bd[4];
            unsigned int bu;
            bu = __float_as_uint(bb.x);
            asm("mov.b64 %0, {%1, %1};" : "=l"(bd[0]) : "r"(bu));
            bu = __float_as_uint(bb.y);
            asm("mov.b64 %0, {%1, %1};" : "=l"(bd[1]) : "r"(bu));
            bu = __float_as_uint(bb.z);
            asm("mov.b64 %0, {%1, %1};" : "=l"(bd[2]) : "r"(bu));
            bu = __float_as_uint(bb.w);
            asm("mov.b64 %0, {%1, %1};" : "=l"(bd[3]) : "r"(bu));
#pragma unroll
            for (int p = 0; p < 4; p++)
#pragma unroll
                for (int j = 0; j < 4; j++)
                    asm("fma.rn.f32x2 %0, %1, %2, %0;"
                        : "+l"(acc2[p][j]) : "l"(ap[p]), "l"(bd[j]));
        }

        if (t + 1 < nt) asm volatile("cp.async.wait_group 0;");
        __syncthreads();
        buf ^= 1;
    }

    // Epilogue: unpack pairs, add bias, store float4 per row
    int gt = t0 + tx * 4;
    if (gt < T_LEN) {
#pragma unroll
        for (int p = 0; p < 4; p++) {
            float lo[4], hi[4];
#pragma unroll
            for (int j = 0; j < 4; j++) {
                unsigned int ulo, uhi;
                asm("mov.b64 {%0, %1}, %2;" : "=r"(ulo), "=r"(uhi) : "l"(acc2[p][j]));
                lo[j] = __uint_as_float(ulo);
                hi[j] = __uint_as_float(uhi);
            }
            int gmlo = m0 + ty * 8 + 2 * p;
            int gmhi = gmlo + 1;
            if (gmlo < M) {
                float bi = bias[gmlo];
                float4 o = make_float4(lo[0] + bi, lo[1] + bi, lo[2] + bi, lo[3] + bi);
                *reinterpret_cast<float4*>(Cb + (size_t)gmlo * T_LEN + gt) = o;
            }
            if (gmhi < M) {
                float bi = bias[gmhi];
                float4 o = make_float4(hi[0] + bi, hi[1] + bi, hi[2] + bi, hi[3] + bi);
                *reinterpret_cast<float4*>(Cb + (size_t)gmhi * T_LEN + gt) = o;
            }
        }
    }
}

// ---------------------------------------------------------------------------
// Host launcher
// ---------------------------------------------------------------------------
static inline int ceil_div(int a, int b) { return (a + b - 1) / b; }

extern "C" void kernel_launch(void* const* d_in, const int* in_sizes, int n_in,
                              void* d_out, int out_size)
{
    (void)in_sizes; (void)n_in; (void)out_size;

    const float* inputs = (const float*)d_in[0];
    const float* a1_1 = (const float*)d_in[1];
    const float* a2_1 = (const float*)d_in[2];
    const float* b_1  = (const float*)d_in[3];
    const float* W1   = (const float*)d_in[4];
    const float* bias1= (const float*)d_in[5];
    const float* a1_2 = (const float*)d_in[6];
    const float* a2_2 = (const float*)d_in[7];
    const float* b_2  = (const float*)d_in[8];
    const float* W2   = (const float*)d_in[9];
    const float* bias2= (const float*)d_in[10];
    const float* a1_3 = (const float*)d_in[11];
    const float* a2_3 = (const float*)d_in[12];
    const float* b_3  = (const float*)d_in[13];
    const float* W3   = (const float*)d_in[14];
    const float* bias3= (const float*)d_in[15];
    const float* a1_4 = (const float*)d_in[16];
    const float* a2_4 = (const float*)d_in[17];
    const float* b_4  = (const float*)d_in[18];
    const float* W4   = (const float*)d_in[19];
    const float* bias4= (const float*)d_in[20];

    float* out = (float*)d_out;
    float* s4_out   = out;                         // [64, 300, 300]
    float* filt_out = out + (size_t)BATCHN * 300 * T_LEN;

    float *bufA, *bufB, *WtBase;
    cudaGetSymbolAddress((void**)&bufA, g_bufA);
    cudaGetSymbolAddress((void**)&bufB, g_bufB);
    cudaGetSymbolAddress((void**)&WtBase, g_Wt);

    // Constants exactly as the reference builds them (double -> f32 cast)
    double EMd = exp(-1.0 / 8.0);
    double ESd = exp(-1.0 / 2.0);
    float fEM = (float)EMd;                       // RESET_DECAY
    float fA1 = (float)(EMd + ESd);
    float fA2 = (float)(-(EMd * ESd));
    float fB  = (float)((8.0 / 6.0) * (EMd - ESd));

    const int F0 = 300, F1 = 500, F2 = 200, F3 = 500, F4 = 300;

    // Layer GEMM shapes: (M, K)
    const int Ms[4] = {F1, F2, F3, F4};
    const int Ks[4] = {F0, F1, F2, F3};
    int Mpad[4], Kpad[4];
    float* Wts[4];
    const float* Ws[4] = {W1, W2, W3, W4};
    for (int l = 0; l < 4; l++) {
        Mpad[l] = ceil_div(Ms[l], BM) * BM;
        Kpad[l] = ceil_div(Ks[l], BK) * BK;
        Wts[l] = WtBase + (size_t)l * 1024 * 1024;
        int total = Mpad[l] * Kpad[l];
        transpose_pad_kernel<<<ceil_div(total, 256), 256>>>(
            Ws[l], Wts[l], Ms[l], Ks[l], Mpad[l], Kpad[l]);
    }

    const int THREADS = 256;
    auto blocks = [](int rows) { return (rows + 255) / 256; };
    auto ggrid = [&](int l) {
        return dim3((T_LEN + BN - 1) / BN, Mpad[l] / BM, BATCHN);
    };
    const float* biases[4] = {bias1, bias2, bias3, bias4};

    // Layer 1
    int rows0 = BATCHN * F0;
    iir_kernel<<<blocks(rows0), THREADS>>>(inputs, bufA, a1_1, a2_1, b_1, F0, rows0);
    sgemm_bias_kernel<<<ggrid(0), 256>>>(Wts[0], bufA, biases[0], bufB,
                                         Ms[0], Ks[0], Mpad[0], Kpad[0]);

    // Layer 2 (LIF of layer-1 currents fused with layer-2 input IIR)
    int rows1 = BATCHN * F1;
    lif_iir_kernel<<<blocks(rows1), THREADS>>>(bufB, bufA, a1_2, a2_2, b_2, F1, rows1, fEM);
    sgemm_bias_kernel<<<ggrid(1), 256>>>(Wts[1], bufA, biases[1], bufB,
                                         Ms[1], Ks[1], Mpad[1], Kpad[1]);

    // Layer 3
    int rows2 = BATCHN * F2;
    lif_iir_kernel<<<blocks(rows2), THREADS>>>(bufB, bufA, a1_3, a2_3, b_3, F2, rows2, fEM);
    sgemm_bias_kernel<<<ggrid(2), 256>>>(Wts[2], bufA, biases[2], bufB,
                                         Ms[2], Ks[2], Mpad[2], Kpad[2]);

    // Layer 4
    int rows3 = BATCHN * F3;
    lif_iir_kernel<<<blocks(rows3), THREADS>>>(bufB, bufA, a1_4, a2_4, b_4, F3, rows3, fEM);
    sgemm_bias_kernel<<<ggrid(3), 256>>>(Wts[3], bufA, biases[3], bufB,
                                         Ms[3], Ks[3], Mpad[3], Kpad[3]);

    // Final: LIF -> s4, fixed output IIR -> filt
    int rows4 = BATCHN * F4;
    lif_final_kernel<<<blocks(rows4), THREADS>>>(bufB, s4_out, filt_out, rows4,
                                                 fEM, fA1, fA2, fB);
}